// round 10
// baseline (speedup 1.0000x reference)
#include <cuda_runtime.h>

#define N_NODES 50000
#define N_EDGES 800000
#define D_IN 64
#define D_OUT 64
#define E_DIM 32
#define NK 96
#define BN_EPS 1e-5f
#define NT32 ((N_NODES + 31) / 32)    // 1563
#define H_STRIDE 100                   // 96 + 4 pad (stride%32==4 -> conflict-free)
#define O_STRIDE 68                    // 64 + 4 pad

typedef unsigned long long ull;

#define FMA2(acc, a, b) \
    asm("fma.rn.f32x2 %0, %1, %2, %3;" : "=l"(acc) : "l"(a), "l"(b), "l"(acc))
#define PACK2(out, lo, hi) \
    asm("mov.b64 %0, {%1, %2};" : "=l"(out) : "f"(lo), "f"(hi))
#define UNPACK2(lo, hi, in) \
    asm("mov.b64 {%0, %1}, %2;" : "=f"(lo), "=f"(hi) : "l"(in))

// ---------------- scratch ----------------
__device__ __align__(16) float g_aggX[N_NODES * D_IN];
__device__ __align__(16) float g_aggE[N_NODES * E_DIM];
__device__ __align__(16) float g_deg[N_NODES];
__device__ __align__(16) float g_h[N_NODES * D_OUT];
__device__ __align__(16) float g_sum[D_OUT];
__device__ __align__(16) float g_sumsq[D_OUT];
__device__ __align__(16) float g_Wall[NK * D_OUT];   // rows 0..63: W1; 64..95: We@W1
__device__ __align__(16) float g_c2[D_OUT];          // be@W1
__device__ __align__(16) float g_scalef[D_OUT];
__device__ __align__(16) float g_shiftf[D_OUT];

// ---------------- kernel 0: zero (R3-proven) ----------------
__global__ void zero_kernel() {
    int idx = blockIdx.x * blockDim.x + threadIdx.x;
    int stride = gridDim.x * blockDim.x;
    float4 z = make_float4(0.f, 0.f, 0.f, 0.f);
    for (int i = idx; i < N_NODES * (D_IN / 4); i += stride) ((float4*)g_aggX)[i] = z;
    for (int i = idx; i < N_NODES * (E_DIM / 4); i += stride) ((float4*)g_aggE)[i] = z;
    for (int i = idx; i < N_NODES; i += stride) g_deg[i] = 0.f;
    if (idx < D_OUT) { g_sum[idx] = 0.f; g_sumsq[idx] = 0.f; }
}

// ---------------- kernel 1: prep Wall = [W1 ; We@W1], c2 = be@W1 ---------------
__global__ void prep_kernel(const float* __restrict__ We,
                            const float* __restrict__ be,
                            const float* __restrict__ W1) {
    __shared__ float W1s[D_IN * D_OUT];
    int tid = threadIdx.x;
    for (int i = tid; i < D_IN * D_OUT; i += 256) W1s[i] = W1[i];
    __syncthreads();
    for (int i = tid; i < D_IN * D_OUT; i += 256) g_Wall[i] = W1s[i];
    for (int i = tid; i < E_DIM * D_OUT; i += 256) {
        int kk = i >> 6, d = i & 63;
        float s = 0.f;
        #pragma unroll 8
        for (int m = 0; m < D_IN; m++) s += We[kk * D_IN + m] * W1s[m * D_OUT + d];
        g_Wall[D_IN * D_OUT + i] = s;
    }
    if (tid < D_OUT) {
        float s = 0.f;
        #pragma unroll 8
        for (int m = 0; m < D_IN; m++) s += be[m] * W1s[m * D_OUT + tid];
        g_c2[tid] = s;
    }
}

// ---------------- kernel 2: edge scatter (R3-proven, byte-identical) -----------
__global__ void edge_kernel(const float4* __restrict__ x4,
                            const int* __restrict__ ei,
                            const float4* __restrict__ ea4) {
    int gwarp = (blockIdx.x * blockDim.x + threadIdx.x) >> 5;
    int lane = threadIdx.x & 31;
    int e0 = gwarp * 2;
    if (e0 >= N_EDGES) return;

    int half = lane >> 4, li = lane & 15;
    int e = e0 + half;
    bool v = (e < N_EDGES);
    int src = 0, dst = 0;
    if (v) {
        src = __ldg(&ei[e]);
        dst = __ldg(&ei[N_EDGES + e]);
    }
    if (v) {
        float4 xv = __ldg(&x4[(size_t)src * (D_IN / 4) + li]);
        atomicAdd(((float4*)(g_aggX + (size_t)dst * D_IN)) + li, xv);
    }
    int dA = __shfl_sync(0xffffffffu, dst, 0);
    int dB = __shfl_sync(0xffffffffu, dst, 16);
    if (lane < 16) {
        int e2 = e0 + (lane >> 3);
        if (e2 < N_EDGES) {
            int d2 = (lane < 8) ? dA : dB;
            int lj = lane & 7;
            float4 av = __ldg(&ea4[(size_t)e2 * (E_DIM / 4) + lj]);
            atomicAdd(((float4*)(g_aggE + (size_t)d2 * E_DIM)) + lj, av);
        }
    } else if (lane < 18) {
        int e3 = e0 + (lane - 16);
        if (e3 < N_EDGES) atomicAdd(&g_deg[(lane == 16) ? dA : dB], 1.f);
    }
}

// ---------------- kernel 3: node_h ----------------
// 32 rows/block. thread: row = lane (within block's 32), dims d0 = warp*8.
// 4 packed f32x2 accumulators. Staging row-major stride 100 (conflict-free).
__global__ __launch_bounds__(256) void node_h_kernel(const float* __restrict__ x,
                                                     const float* __restrict__ b1) {
    __shared__ __align__(16) float Ws[NK * D_OUT];        // 24KB
    __shared__ __align__(16) float stS[32 * H_STRIDE];    // 12.8KB

    int tid = threadIdx.x;
    #pragma unroll
    for (int i = 0; i < 6; i++)
        ((float4*)Ws)[tid + i * 256] = ((const float4*)g_Wall)[tid + i * 256];

    int rowBase = blockIdx.x * 32;
    // ---- stage: thread -> row tid>>3, chunks 3*(tid&7)+{0,1,2} ----
    {
        int rr = tid >> 3;
        int i8 = tid & 7;
        int row = rowBase + rr;
        float* dstRow = stS + rr * H_STRIDE;
        #pragma unroll
        for (int j = 0; j < 3; j++) {
            int c = 3 * i8 + j;           // 0..23
            float4 v = make_float4(0.f, 0.f, 0.f, 0.f);
            if (row < N_NODES) {
                if (c < 16) {
                    float4 a = ((const float4*)g_aggX)[(size_t)row * 16 + c];
                    float4 xv = __ldg(&((const float4*)x)[(size_t)row * 16 + c]);
                    v = make_float4(a.x + xv.x, a.y + xv.y, a.z + xv.z, a.w + xv.w);
                } else {
                    v = ((const float4*)g_aggE)[(size_t)row * 8 + (c - 16)];
                }
            }
            *(float4*)(dstRow + c * 4) = v;
        }
    }
    __syncthreads();

    int w = tid >> 5, lane = tid & 31;
    int d0 = w * 8;
    int row = rowBase + lane;
    bool valid = (row < N_NODES);
    float deg = valid ? g_deg[row] : 0.f;
    ull deg2; PACK2(deg2, deg, deg);

    ull acc[4];
    {
        const ull* b1p = (const ull*)(b1 + d0);
        const ull* c2p = (const ull*)(g_c2 + d0);
        #pragma unroll
        for (int i = 0; i < 4; i++) { acc[i] = __ldg(&b1p[i]); FMA2(acc[i], deg2, __ldg(&c2p[i])); }
    }

    const float* arow = stS + lane * H_STRIDE;
    #pragma unroll 6
    for (int k4 = 0; k4 < NK / 4; k4++) {
        float4 a4 = *(const float4*)(arow + k4 * 4);
        float av[4] = {a4.x, a4.y, a4.z, a4.w};
        #pragma unroll
        for (int j = 0; j < 4; j++) {
            ull a2; PACK2(a2, av[j], av[j]);
            const ulonglong2* wp = (const ulonglong2*)(Ws + (k4 * 4 + j) * D_OUT + d0);
            ulonglong2 w0 = wp[0], w1 = wp[1];
            FMA2(acc[0], a2, w0.x); FMA2(acc[1], a2, w0.y);
            FMA2(acc[2], a2, w1.x); FMA2(acc[3], a2, w1.y);
        }
    }

    // store h + per-thread stats
    float hv[8];
    #pragma unroll
    for (int i = 0; i < 4; i++) UNPACK2(hv[2 * i], hv[2 * i + 1], acc[i]);
    if (valid) {
        ulonglong2* hrow = (ulonglong2*)(g_h + (size_t)row * 64 + d0);
        ulonglong2 v0; v0.x = acc[0]; v0.y = acc[1];
        ulonglong2 v1; v1.x = acc[2]; v1.y = acc[3];
        hrow[0] = v0; hrow[1] = v1;
    }
    float s[8], q[8];
    #pragma unroll
    for (int i = 0; i < 8; i++) {
        s[i] = valid ? hv[i] : 0.f;
        q[i] = s[i] * s[i];
    }
    // warp-reduce across rows (all lanes share dim range d0..d0+7)
    #pragma unroll
    for (int off = 16; off > 0; off >>= 1) {
        #pragma unroll
        for (int i = 0; i < 8; i++) {
            s[i] += __shfl_down_sync(0xffffffffu, s[i], off);
            q[i] += __shfl_down_sync(0xffffffffu, q[i], off);
        }
    }
    if (lane < 8) {
        float sv = __shfl_sync(0xffffffffu, s[lane], 0);  // wrong lane source fix below
    }
    if (lane == 0) {
        #pragma unroll
        for (int i = 0; i < 8; i++) {
            atomicAdd(&g_sum[d0 + i], s[i]);
            atomicAdd(&g_sumsq[d0 + i], q[i]);
        }
    }
}

// ---------------- kernel 4: bn finalize ----------------
__global__ void bn_kernel(const float* __restrict__ gamma,
                          const float* __restrict__ beta) {
    int d = threadIdx.x;   // 64
    float n = (float)N_NODES;
    float mean = g_sum[d] / n;
    float var = g_sumsq[d] / n - mean * mean;
    float rstd = rsqrtf(var + BN_EPS);
    float sc = gamma[d] * rstd;
    g_scalef[d] = sc;
    g_shiftf[d] = beta[d] - mean * sc;
}

// ---------------- kernel 5: node_out ----------------
__global__ __launch_bounds__(256) void node_out_kernel(const float* __restrict__ W2,
                                                       const float* __restrict__ b2,
                                                       float* __restrict__ out) {
    __shared__ __align__(16) float Ws[D_OUT * D_OUT];     // 16KB
    __shared__ __align__(16) float stS[32 * O_STRIDE];    // 8.7KB
    __shared__ __align__(16) float scf[D_OUT], shf[D_OUT];

    int tid = threadIdx.x;
    #pragma unroll
    for (int i = 0; i < 4; i++)
        ((float4*)Ws)[tid + i * 256] = __ldg(&((const float4*)W2)[tid + i * 256]);
    if (tid < D_OUT) { scf[tid] = g_scalef[tid]; shf[tid] = g_shiftf[tid]; }
    __syncthreads();

    int rowBase = blockIdx.x * 32;
    // ---- stage relu(bn(h)): thread -> row tid>>3, chunks 2*(tid&7)+{0,1} ----
    {
        int rr = tid >> 3;
        int i8 = tid & 7;
        int row = rowBase + rr;
        float* dstRow = stS + rr * O_STRIDE;
        #pragma unroll
        for (int j = 0; j < 2; j++) {
            int c = 2 * i8 + j;           // 0..15
            float4 v = make_float4(0.f, 0.f, 0.f, 0.f);
            if (row < N_NODES) {
                float4 hv = ((const float4*)g_h)[(size_t)row * 16 + c];
                float4 sc = ((const float4*)scf)[c];
                float4 sh = ((const float4*)shf)[c];
                v.x = fmaxf(0.f, hv.x * sc.x + sh.x);
                v.y = fmaxf(0.f, hv.y * sc.y + sh.y);
                v.z = fmaxf(0.f, hv.z * sc.z + sh.z);
                v.w = fmaxf(0.f, hv.w * sc.w + sh.w);
            }
            *(float4*)(dstRow + c * 4) = v;
        }
    }
    __syncthreads();

    int w = tid >> 5, lane = tid & 31;
    int d0 = w * 8;
    int row = rowBase + lane;

    ull acc[4];
    {
        const ull* b2p = (const ull*)(b2 + d0);
        #pragma unroll
        for (int i = 0; i < 4; i++) acc[i] = __ldg(&b2p[i]);
    }

    const float* arow = stS + lane * O_STRIDE;
    #pragma unroll 4
    for (int k4 = 0; k4 < D_OUT / 4; k4++) {
        float4 a4 = *(const float4*)(arow + k4 * 4);
        float av[4] = {a4.x, a4.y, a4.z, a4.w};
        #pragma unroll
        for (int j = 0; j < 4; j++) {
            ull a2; PACK2(a2, av[j], av[j]);
            const ulonglong2* wp = (const ulonglong2*)(Ws + (k4 * 4 + j) * D_OUT + d0);
            ulonglong2 w0 = wp[0], w1 = wp[1];
            FMA2(acc[0], a2, w0.x); FMA2(acc[1], a2, w0.y);
            FMA2(acc[2], a2, w1.x); FMA2(acc[3], a2, w1.y);
        }
    }

    if (row < N_NODES) {
        ulonglong2* orow = (ulonglong2*)(out + (size_t)row * 64 + d0);
        ulonglong2 v0; v0.x = acc[0]; v0.y = acc[1];
        ulonglong2 v1; v1.x = acc[2]; v1.y = acc[3];
        orow[0] = v0; orow[1] = v1;
    }
}

// ---------------- launch ----------------
extern "C" void kernel_launch(void* const* d_in, const int* in_sizes, int n_in,
                              void* d_out, int out_size) {
    const float* x     = (const float*)d_in[0];
    const int* ei      = (const int*)d_in[1];
    const float* ea    = (const float*)d_in[2];
    const float* We    = (const float*)d_in[3];
    const float* be    = (const float*)d_in[4];
    const float* W1    = (const float*)d_in[5];
    const float* b1    = (const float*)d_in[6];
    const float* gamma = (const float*)d_in[7];
    const float* beta  = (const float*)d_in[8];
    const float* W2    = (const float*)d_in[9];
    const float* b2    = (const float*)d_in[10];
    float* out         = (float*)d_out;

    zero_kernel<<<2048, 256>>>();
    prep_kernel<<<1, 256>>>(We, be, W1);

    int nWarps = (N_EDGES + 1) / 2;
    int nBlocks = (nWarps + 7) / 8;
    edge_kernel<<<nBlocks, 256>>>((const float4*)x, ei, (const float4*)ea);

    node_h_kernel<<<NT32, 256>>>(x, b1);
    bn_kernel<<<1, 64>>>(gamma, beta);
    node_out_kernel<<<NT32, 256>>>(W2, b2, out);
}

// round 11
// speedup vs baseline: 1.3507x; 1.3507x over previous
#include <cuda_runtime.h>

#define N_NODES 50000
#define N_EDGES 800000
#define D_IN 64
#define D_OUT 64
#define E_DIM 32
#define BN_EPS 1e-5f

// ---------------- scratch ----------------
__device__ __align__(16) float g_aggX[N_NODES * D_IN];
__device__ __align__(16) float g_aggE[N_NODES * E_DIM];
__device__ __align__(16) float g_h[N_NODES * D_OUT];
__device__ int g_cnt[N_NODES];
__device__ int g_locpre[65536];
__device__ int g_part[256];
__device__ int g_partoff[256];
__device__ int g_rowstart[N_NODES + 1];
__device__ int g_cursor[N_NODES];
__device__ int g_esrc[N_EDGES];
__device__ __align__(16) float g_sum[D_OUT];
__device__ __align__(16) float g_sumsq[D_OUT];
__device__ __align__(16) float g_C1[E_DIM * D_OUT];   // We @ W1
__device__ __align__(16) float g_c2[D_OUT];           // be @ W1
__device__ __align__(16) float g_scale[D_OUT];
__device__ __align__(16) float g_shift[D_OUT];

// ---------------- kernel 0: zero (aggE, cnt, stats; aggX overwritten by gather) -
__global__ void zero_kernel() {
    int idx = blockIdx.x * blockDim.x + threadIdx.x;
    int stride = gridDim.x * blockDim.x;
    float4 z = make_float4(0.f, 0.f, 0.f, 0.f);
    for (int i = idx; i < N_NODES * (E_DIM / 4); i += stride) ((float4*)g_aggE)[i] = z;
    for (int i = idx; i < N_NODES; i += stride) g_cnt[i] = 0;
    if (idx < D_OUT) { g_sum[idx] = 0.f; g_sumsq[idx] = 0.f; }
}

// ---------------- kernel 1: prep C1 = We@W1, c2 = be@W1 (R3-proven) -----------
__global__ void prep_kernel(const float* __restrict__ We,
                            const float* __restrict__ be,
                            const float* __restrict__ W1) {
    int tid = threadIdx.x;
    for (int idx = tid; idx < E_DIM * D_OUT; idx += blockDim.x) {
        int k = idx >> 6, d = idx & 63;
        float s = 0.f;
        #pragma unroll 8
        for (int m = 0; m < D_IN; m++) s += We[k * D_IN + m] * W1[m * D_OUT + d];
        g_C1[idx] = s;
    }
    if (tid < D_OUT) {
        float s = 0.f;
        #pragma unroll 8
        for (int m = 0; m < D_IN; m++) s += be[m] * W1[m * D_OUT + tid];
        g_c2[tid] = s;
    }
}

// ---------------- CSR build (R6-proven machinery, esrc only) -------------------
__global__ void hist_kernel(const int* __restrict__ ei) {
    int e = blockIdx.x * blockDim.x + threadIdx.x;
    if (e < N_EDGES) atomicAdd(&g_cnt[ei[N_EDGES + e]], 1);
}

__global__ void scan1_kernel() {   // 256 blocks x 256
    __shared__ int sd[256];
    int t = threadIdx.x;
    int g = blockIdx.x * 256 + t;
    int v = (g < N_NODES) ? g_cnt[g] : 0;
    sd[t] = v;
    __syncthreads();
    #pragma unroll
    for (int off = 1; off < 256; off <<= 1) {
        int y = (t >= off) ? sd[t - off] : 0;
        __syncthreads();
        sd[t] += y;
        __syncthreads();
    }
    g_locpre[g] = sd[t] - v;
    if (t == 255) g_part[blockIdx.x] = sd[255];
}

__global__ void scan2_kernel() {   // 1 block x 256
    __shared__ int sd[256];
    int t = threadIdx.x;
    int v = g_part[t];
    sd[t] = v;
    __syncthreads();
    #pragma unroll
    for (int off = 1; off < 256; off <<= 1) {
        int y = (t >= off) ? sd[t - off] : 0;
        __syncthreads();
        sd[t] += y;
        __syncthreads();
    }
    g_partoff[t] = sd[t] - v;
}

__global__ void scan3_kernel() {   // 256 blocks x 256
    int t = threadIdx.x;
    int g = blockIdx.x * 256 + t;
    if (g < N_NODES) {
        int rs = g_locpre[g] + g_partoff[blockIdx.x];
        g_rowstart[g] = rs;
        g_cursor[g] = rs;
    }
    if (g == 0) g_rowstart[N_NODES] = N_EDGES;
}

__global__ void scatter_kernel(const int* __restrict__ ei) {
    int e = blockIdx.x * blockDim.x + threadIdx.x;
    if (e >= N_EDGES) return;
    int dst = ei[N_EDGES + e];
    int pos = atomicAdd(&g_cursor[dst], 1);
    g_esrc[pos] = ei[e];
}

// ---------------- ea scatter: streaming reads + float4 REDs --------------------
// Warp handles 4 edges: lane = edge-quarter (lane>>3) x chunk (lane&7).
__global__ void ea_kernel(const int* __restrict__ ei,
                          const float4* __restrict__ ea4) {
    int gwarp = (blockIdx.x * blockDim.x + threadIdx.x) >> 5;
    int lane = threadIdx.x & 31;
    int e = gwarp * 4 + (lane >> 3);
    if (e >= N_EDGES) return;
    int li = lane & 7;
    int dst = __ldg(&ei[N_EDGES + e]);
    float4 av = __ldg(&ea4[(size_t)e * (E_DIM / 4) + li]);
    atomicAdd(((float4*)(g_aggE + (size_t)dst * E_DIM)) + li, av);
}

// ---------------- gather x: warp per node, 8 edges in flight, no atomics -------
__global__ void gather_x_kernel(const float4* __restrict__ x4) {
    int gw = (blockIdx.x * blockDim.x + threadIdx.x) >> 5;
    if (gw >= N_NODES) return;
    int lane = threadIdx.x & 31;
    int half = lane >> 4, li = lane & 15;
    int start = g_rowstart[gw], end = g_rowstart[gw + 1];
    float4 acc = make_float4(0.f, 0.f, 0.f, 0.f);
    int p = start;
    for (; p + 8 <= end; p += 8) {
        int s0 = __ldg(&g_esrc[p + half]);
        int s1 = __ldg(&g_esrc[p + 2 + half]);
        int s2 = __ldg(&g_esrc[p + 4 + half]);
        int s3 = __ldg(&g_esrc[p + 6 + half]);
        float4 v0 = __ldg(&x4[(size_t)s0 * 16 + li]);
        float4 v1 = __ldg(&x4[(size_t)s1 * 16 + li]);
        float4 v2 = __ldg(&x4[(size_t)s2 * 16 + li]);
        float4 v3 = __ldg(&x4[(size_t)s3 * 16 + li]);
        acc.x += (v0.x + v1.x) + (v2.x + v3.x);
        acc.y += (v0.y + v1.y) + (v2.y + v3.y);
        acc.z += (v0.z + v1.z) + (v2.z + v3.z);
        acc.w += (v0.w + v1.w) + (v2.w + v3.w);
    }
    for (int e = p + half; e < end; e += 2) {
        int s = __ldg(&g_esrc[e]);
        float4 v = __ldg(&x4[(size_t)s * 16 + li]);
        acc.x += v.x; acc.y += v.y; acc.z += v.z; acc.w += v.w;
    }
    acc.x += __shfl_down_sync(0xffffffffu, acc.x, 16);
    acc.y += __shfl_down_sync(0xffffffffu, acc.y, 16);
    acc.z += __shfl_down_sync(0xffffffffu, acc.z, 16);
    acc.w += __shfl_down_sync(0xffffffffu, acc.w, 16);
    if (half == 0) ((float4*)g_aggX)[(size_t)gw * 16 + li] = acc;
}

// ---------------- node_h (R3-proven; deg from rowstart) ------------------------
__global__ void node_h_kernel(const float* __restrict__ x,
                              const float* __restrict__ W1,
                              const float* __restrict__ b1) {
    __shared__ __align__(16) float W1s[D_IN * D_OUT];
    __shared__ __align__(16) float C1s[E_DIM * D_OUT];
    __shared__ float c2s[D_OUT], b1s[D_OUT];
    __shared__ __align__(16) float rv[8][4][D_IN];
    __shared__ __align__(16) float ra[8][4][E_DIM];
    __shared__ float bsum[D_OUT], bsq[D_OUT];

    int tid = threadIdx.x;
    for (int i = tid; i < D_IN * D_OUT; i += 256) W1s[i] = W1[i];
    for (int i = tid; i < E_DIM * D_OUT; i += 256) C1s[i] = g_C1[i];
    if (tid < D_OUT) { c2s[tid] = g_c2[tid]; b1s[tid] = b1[tid]; bsum[tid] = 0.f; bsq[tid] = 0.f; }
    __syncthreads();

    int warp = tid >> 5, lane = tid & 31;
    int d = lane;
    float s0 = 0.f, q0 = 0.f, s1 = 0.f, q1 = 0.f;

    int nGroups = (N_NODES + 31) / 32;
    for (int g = blockIdx.x; g < nGroups; g += gridDim.x) {
        int rowBase = g * 32 + warp * 4;
        #pragma unroll
        for (int r = 0; r < 4; r++) {
            int row = rowBase + r;
            if (row < N_NODES) {
                if (lane < 16) {
                    float4 a = ((const float4*)g_aggX)[row * 16 + lane];
                    float4 xv = __ldg(&((const float4*)x)[row * 16 + lane]);
                    a.x += xv.x; a.y += xv.y; a.z += xv.z; a.w += xv.w;
                    ((float4*)&rv[warp][r][0])[lane] = a;
                } else if (lane < 24) {
                    int lj = lane - 16;
                    ((float4*)&ra[warp][r][0])[lj] = ((const float4*)g_aggE)[row * 8 + lj];
                }
            }
        }
        __syncwarp();

        float h[4][2];
        #pragma unroll
        for (int r = 0; r < 4; r++) {
            int row = rowBase + r;
            float dg = 0.f;
            if (row < N_NODES) dg = (float)(g_rowstart[row + 1] - g_rowstart[row]);
            h[r][0] = dg * c2s[d] + b1s[d];
            h[r][1] = dg * c2s[d + 32] + b1s[d + 32];
        }
        #pragma unroll 8
        for (int k = 0; k < D_IN; k++) {
            float w0 = W1s[k * D_OUT + d];
            float w1 = W1s[k * D_OUT + d + 32];
            #pragma unroll
            for (int r = 0; r < 4; r++) {
                float a = rv[warp][r][k];
                h[r][0] += a * w0; h[r][1] += a * w1;
            }
        }
        #pragma unroll 8
        for (int k = 0; k < E_DIM; k++) {
            float w0 = C1s[k * D_OUT + d];
            float w1 = C1s[k * D_OUT + d + 32];
            #pragma unroll
            for (int r = 0; r < 4; r++) {
                float a = ra[warp][r][k];
                h[r][0] += a * w0; h[r][1] += a * w1;
            }
        }
        #pragma unroll
        for (int r = 0; r < 4; r++) {
            int row = rowBase + r;
            if (row < N_NODES) {
                g_h[row * D_OUT + d] = h[r][0];
                g_h[row * D_OUT + d + 32] = h[r][1];
                s0 += h[r][0]; q0 += h[r][0] * h[r][0];
                s1 += h[r][1]; q1 += h[r][1] * h[r][1];
            }
        }
        __syncwarp();
    }

    atomicAdd(&bsum[d], s0);      atomicAdd(&bsq[d], q0);
    atomicAdd(&bsum[d + 32], s1); atomicAdd(&bsq[d + 32], q1);
    __syncthreads();
    if (tid < D_OUT) {
        atomicAdd(&g_sum[tid], bsum[tid]);
        atomicAdd(&g_sumsq[tid], bsq[tid]);
    }
}

// ---------------- bn finalize (R3-proven) ----------------
__global__ void bn_kernel(const float* __restrict__ gamma,
                          const float* __restrict__ beta) {
    int d = threadIdx.x;
    float n = (float)N_NODES;
    float mean = g_sum[d] / n;
    float var = g_sumsq[d] / n - mean * mean;
    float rstd = rsqrtf(var + BN_EPS);
    float sc = gamma[d] * rstd;
    g_scale[d] = sc;
    g_shift[d] = beta[d] - mean * sc;
}

// ---------------- node_out (R3-proven, byte-identical) ----------------
__global__ void node_out_kernel(const float* __restrict__ W2,
                                const float* __restrict__ b2,
                                float* __restrict__ out) {
    __shared__ __align__(16) float W2s[D_OUT * D_OUT];
    __shared__ __align__(16) float rs[8][4][D_OUT];
    __shared__ __align__(16) float scs[D_OUT];
    __shared__ __align__(16) float shs[D_OUT];
    __shared__ float b2s[D_OUT];

    int tid = threadIdx.x;
    for (int i = tid; i < D_OUT * D_OUT; i += 256) W2s[i] = W2[i];
    if (tid < D_OUT) { scs[tid] = g_scale[tid]; shs[tid] = g_shift[tid]; b2s[tid] = b2[tid]; }
    __syncthreads();

    int warp = tid >> 5, lane = tid & 31;
    int d = lane;

    int nGroups = (N_NODES + 31) / 32;
    for (int g = blockIdx.x; g < nGroups; g += gridDim.x) {
        int rowBase = g * 32 + warp * 4;
        #pragma unroll
        for (int r = 0; r < 4; r++) {
            int row = rowBase + r;
            if (row < N_NODES && lane < 16) {
                float4 hv = ((const float4*)g_h)[row * 16 + lane];
                float4 sc = ((const float4*)scs)[lane];
                float4 sh = ((const float4*)shs)[lane];
                float4 v;
                v.x = fmaxf(0.f, hv.x * sc.x + sh.x);
                v.y = fmaxf(0.f, hv.y * sc.y + sh.y);
                v.z = fmaxf(0.f, hv.z * sc.z + sh.z);
                v.w = fmaxf(0.f, hv.w * sc.w + sh.w);
                ((float4*)&rs[warp][r][0])[lane] = v;
            }
        }
        __syncwarp();

        float y[4][2];
        #pragma unroll
        for (int r = 0; r < 4; r++) { y[r][0] = b2s[d]; y[r][1] = b2s[d + 32]; }
        #pragma unroll 8
        for (int k = 0; k < D_OUT; k++) {
            float w0 = W2s[k * D_OUT + d];
            float w1 = W2s[k * D_OUT + d + 32];
            #pragma unroll
            for (int r = 0; r < 4; r++) {
                float a = rs[warp][r][k];
                y[r][0] += a * w0; y[r][1] += a * w1;
            }
        }
        #pragma unroll
        for (int r = 0; r < 4; r++) {
            int row = rowBase + r;
            if (row < N_NODES) {
                out[row * D_OUT + d] = y[r][0];
                out[row * D_OUT + d + 32] = y[r][1];
            }
        }
        __syncwarp();
    }
}

// ---------------- launch ----------------
extern "C" void kernel_launch(void* const* d_in, const int* in_sizes, int n_in,
                              void* d_out, int out_size) {
    const float* x     = (const float*)d_in[0];
    const int* ei      = (const int*)d_in[1];
    const float* ea    = (const float*)d_in[2];
    const float* We    = (const float*)d_in[3];
    const float* be    = (const float*)d_in[4];
    const float* W1    = (const float*)d_in[5];
    const float* b1    = (const float*)d_in[6];
    const float* gamma = (const float*)d_in[7];
    const float* beta  = (const float*)d_in[8];
    const float* W2    = (const float*)d_in[9];
    const float* b2    = (const float*)d_in[10];
    float* out         = (float*)d_out;

    zero_kernel<<<1024, 256>>>();
    prep_kernel<<<1, 256>>>(We, be, W1);

    // CSR build for x-side
    hist_kernel<<<(N_EDGES + 255) / 256, 256>>>(ei);
    scan1_kernel<<<256, 256>>>();
    scan2_kernel<<<1, 256>>>();
    scan3_kernel<<<256, 256>>>();
    scatter_kernel<<<(N_EDGES + 255) / 256, 256>>>(ei);

    // ea-side: streaming atomics (4 edges/warp, 8 warps/block)
    ea_kernel<<<(N_EDGES / 4 + 7) / 8, 256>>>(ei, (const float4*)ea);

    // x-side: CSR gather, warp per node
    gather_x_kernel<<<(N_NODES * 32 + 255) / 256, 256>>>((const float4*)x);

    node_h_kernel<<<592, 256>>>(x, W1, b1);
    bn_kernel<<<1, 64>>>(gamma, beta);
    node_out_kernel<<<592, 256>>>(W2, b2, out);
}